// round 6
// baseline (speedup 1.0000x reference)
#include <cuda_runtime.h>
#include <math.h>
#include <stdint.h>

#define BDIM 8
#define HW 64
#define CMID 576
#define CCAT 1632
#define EPSV 1e-5f

// ---------------------------------------------------------------------------
// Scratch (device globals: allocation-free per harness rules)
// ---------------------------------------------------------------------------
__device__ float g_cat1[BDIM * CMID * HW * HW];
__device__ float g_cat2[BDIM * CCAT * HW * HW];
__device__ float g_mid [BDIM * CMID * HW * HW];
__device__ float g_mid2[BDIM * CMID * HW * HW];
__device__ float g_small[BDIM * HW * HW];
__device__ float g_wt_dec[9 * CMID * CMID];
__device__ float g_wt_cc [9 * CMID * CCAT];
__device__ float g_wt_o1 [9 * CMID * CMID];

// ---------------------------------------------------------------------------
// helpers
// ---------------------------------------------------------------------------
__device__ __forceinline__ uint32_t f2tf32(float f) {
    uint32_t o;
    asm("cvt.rna.tf32.f32 %0, %1;" : "=r"(o) : "f"(f));
    return o;
}
__device__ __forceinline__ void mma_tf32(float* d, const uint32_t* a, const uint32_t* b) {
    asm volatile(
        "mma.sync.aligned.m16n8k8.row.col.f32.tf32.tf32.f32 "
        "{%0,%1,%2,%3}, {%4,%5,%6,%7}, {%8,%9}, {%0,%1,%2,%3};"
        : "+f"(d[0]), "+f"(d[1]), "+f"(d[2]), "+f"(d[3])
        : "r"(a[0]), "r"(a[1]), "r"(a[2]), "r"(a[3]), "r"(b[0]), "r"(b[1]));
}

// ---------------------------------------------------------------------------
// Weight transpose + tf32 round: OIHW [co][ci][p] -> [p][co][ci]
// ---------------------------------------------------------------------------
__global__ void wtrans(const float* __restrict__ w, float* __restrict__ wt, int CoCi) {
    __shared__ float s[2304];
    int base = blockIdx.x * 256;
    int t = threadIdx.x;
    for (int i = t; i < 2304; i += 256) s[i] = w[(size_t)base * 9 + i];
    __syncthreads();
#pragma unroll
    for (int p = 0; p < 9; p++)
        wt[(size_t)p * CoCi + base + t] = __uint_as_float(f2tf32(s[t * 9 + p]));
}

// ---------------------------------------------------------------------------
// pack kernels
// ---------------------------------------------------------------------------
__global__ void pack_cat1(const float* __restrict__ coarse,
                          const float* __restrict__ raw) {
    int idx = blockIdx.x * blockDim.x + threadIdx.x;
    const int N = BDIM * CMID * HW * HW;
    if (idx >= N) return;
    int x = idx & 63;
    int y = (idx >> 6) & 63;
    int c = (idx >> 12) % CMID;
    int b = idx / (CMID * HW * HW);
    float v;
    if (c < 384) {
        v = coarse[((b * 384 + c) << 12) + (y << 6) + x];
    } else {
        int pc = c - 384;
        int gy = pc / 24;
        int r  = pc - gy * 24;
        int gx = r / 3;
        int cc = r - gx * 3;
        v = raw[((b * 3 + cc) * 512 + gy * 64 + y) * 512 + gx * 64 + x];
    }
    g_cat1[idx] = v;
}

__global__ void pack_sides(const float* __restrict__ x2,
                           const float* __restrict__ x3) {
    int idx = blockIdx.x * blockDim.x + threadIdx.x;
    const int N2 = BDIM * 768 * HW * HW;
    const int N3 = BDIM * 288 * HW * HW;
    if (idx < N2) {
        int b = idx / (768 * 4096);
        int r = idx - b * 768 * 4096;
        g_cat2[b * CCAT * 4096 + r] = x2[idx];
    } else if (idx < N2 + N3) {
        int j = idx - N2;
        int b = j / (288 * 4096);
        int r = j - b * 288 * 4096;
        g_cat2[b * CCAT * 4096 + 1344 * 4096 + r] = x3[j];
    }
}

// ---------------------------------------------------------------------------
// conv3x3 + folded BN via mma.sync tf32 implicit GEMM.
//   CTA: M=256 pixels (4 rows of one image) x N=64 couts; 512 thr, 16 warps.
//   Warp grid 8(M) x 2(N): warp tile 32x32 -> 2 m-frags x 4 n-frags m16n8k8.
//   K loop: cin chunks of 16. Per chunk: stage halo (16c x 6r x 66x, tf32)
//   + all-9-position B tiles; A fragments read straight from halo with
//   (ky,kx) shifts. Next chunk's globals prefetched into regs during mma.
// ---------------------------------------------------------------------------
#define HALO_ROWP 68
#define HALO_CSTR (6 * HALO_ROWP)         // 408
#define HALO_F    (16 * HALO_CSTR)        // 6528 floats
#define B_NSTR    72
#define B_POSSTR  (16 * B_NSTR)           // 1152
#define B_F       (9 * B_POSSTR)          // 10368 floats
#define SMEM_BYTES ((HALO_F + B_F) * 4)   // 67584
#define HITER 13                          // ceil(6336/512)
#define BITER 18                          // 9216/512

__global__ void __launch_bounds__(512, 1)
conv3x3_tc(const float* __restrict__ in, int Cin,
           const float* __restrict__ wt,
           const float* __restrict__ gam, const float* __restrict__ bet,
           const float* __restrict__ mu,  const float* __restrict__ var,
           float* __restrict__ out, int Ctot, int Coff) {
    extern __shared__ float sm[];
    float* sh = sm;            // halo
    float* sB = sm + HALO_F;   // B tiles

    int tid = threadIdx.x;
    int wid = tid >> 5;
    int lid = tid & 31;
    int l4  = lid >> 2;
    int kc  = lid & 3;
    int mw  = wid & 7;          // 8 m-warps
    int nw  = wid >> 3;         // 2 n-warps

    int tile = blockIdx.x;      // 128 tiles: b = t>>4, 4 rows each
    int b  = tile >> 4;
    int y0 = (tile & 15) << 2;
    int cbase = blockIdx.y * 64;

    const float* ib = in + (size_t)b * Cin * 4096;

    float d[2][4][4];
#pragma unroll
    for (int mi = 0; mi < 2; mi++)
#pragma unroll
        for (int ni = 0; ni < 4; ni++)
#pragma unroll
            for (int j = 0; j < 4; j++) d[mi][ni][j] = 0.f;

    // per-thread A-fragment geometry (same for every chunk)
    int mm0 = mw * 32 + l4;         // mi=0
    int mm1 = mw * 32 + 16 + l4;    // mi=1
    int ya0 = mm0 >> 6, xa0 = mm0 & 63;
    int ya1 = mm1 >> 6, xa1 = mm1 & 63;

    float hreg[HITER];
    float breg[BITER];

    // prefetch chunk 0
    {
#pragma unroll
        for (int i = 0; i < HITER; i++) {
            int e = tid + i * 512;
            float v = 0.f;
            if (e < 6336) {
                int c   = e / 396;
                int rem = e - c * 396;
                int r   = rem / 66;
                int xx  = rem - r * 66;
                int yg = y0 - 1 + r;
                int xg = xx - 1;
                if ((unsigned)yg < 64u && (unsigned)xg < 64u)
                    v = ib[(size_t)c * 4096 + yg * 64 + xg];
            }
            hreg[i] = v;
        }
#pragma unroll
        for (int i = 0; i < BITER; i++) {
            int idx = tid + i * 512;
            int k = idx & 15;
            int n = (idx >> 4) & 63;
            int pos = idx >> 10;
            breg[i] = wt[((size_t)pos * CMID + cbase + n) * Cin + k];
        }
    }

    int nchunks = Cin >> 4;
    for (int ch = 0; ch < nchunks; ch++) {
        __syncthreads();      // previous chunk's smem readers done
        // ---- store staged regs to smem
#pragma unroll
        for (int i = 0; i < HITER; i++) {
            int e = tid + i * 512;
            if (e < 6336) {
                int c   = e / 396;
                int rem = e - c * 396;
                int r   = rem / 66;
                int xx  = rem - r * 66;
                sh[c * HALO_CSTR + r * HALO_ROWP + xx] =
                    __uint_as_float(f2tf32(hreg[i]));
            }
        }
#pragma unroll
        for (int i = 0; i < BITER; i++) {
            int idx = tid + i * 512;
            int k = idx & 15;
            int n = (idx >> 4) & 63;
            int pos = idx >> 10;
            sB[pos * B_POSSTR + k * B_NSTR + n] = breg[i];
        }
        __syncthreads();

        // ---- prefetch next chunk while mma runs
        if (ch + 1 < nchunks) {
            int ci0 = (ch + 1) << 4;
#pragma unroll
            for (int i = 0; i < HITER; i++) {
                int e = tid + i * 512;
                float v = 0.f;
                if (e < 6336) {
                    int c   = e / 396;
                    int rem = e - c * 396;
                    int r   = rem / 66;
                    int xx  = rem - r * 66;
                    int yg = y0 - 1 + r;
                    int xg = xx - 1;
                    if ((unsigned)yg < 64u && (unsigned)xg < 64u)
                        v = ib[(size_t)(ci0 + c) * 4096 + yg * 64 + xg];
                }
                hreg[i] = v;
            }
#pragma unroll
            for (int i = 0; i < BITER; i++) {
                int idx = tid + i * 512;
                int k = idx & 15;
                int n = (idx >> 4) & 63;
                int pos = idx >> 10;
                breg[i] = wt[((size_t)pos * CMID + cbase + n) * Cin + ci0 + k];
            }
        }

        // ---- compute: 9 positions x 2 k-steps x (2 m-frags x 4 n-frags)
#pragma unroll
        for (int pos = 0; pos < 9; pos++) {
            int ky = pos / 3;
            int kx = pos - ky * 3;
            const float* hb = sh + ky * HALO_ROWP + kx;
            const float* bb = sB + pos * B_POSSTR;
#pragma unroll
            for (int ks = 0; ks < 2; ks++) {
                int k0 = ks << 3;
                uint32_t A[2][4], B[4][2];
                {
                    const float* p0 = hb + (k0 + kc) * HALO_CSTR + ya0 * HALO_ROWP + xa0;
                    A[0][0] = __float_as_uint(p0[0]);
                    A[0][1] = __float_as_uint(p0[8]);
                    A[0][2] = __float_as_uint(p0[4 * HALO_CSTR]);
                    A[0][3] = __float_as_uint(p0[4 * HALO_CSTR + 8]);
                    const float* p1 = hb + (k0 + kc) * HALO_CSTR + ya1 * HALO_ROWP + xa1;
                    A[1][0] = __float_as_uint(p1[0]);
                    A[1][1] = __float_as_uint(p1[8]);
                    A[1][2] = __float_as_uint(p1[4 * HALO_CSTR]);
                    A[1][3] = __float_as_uint(p1[4 * HALO_CSTR + 8]);
                }
#pragma unroll
                for (int ni = 0; ni < 4; ni++) {
                    const float* pb = bb + (k0 + kc) * B_NSTR + nw * 32 + ni * 8 + l4;
                    B[ni][0] = __float_as_uint(pb[0]);
                    B[ni][1] = __float_as_uint(pb[4 * B_NSTR]);
                }
#pragma unroll
                for (int mi = 0; mi < 2; mi++)
#pragma unroll
                    for (int ni = 0; ni < 4; ni++)
                        mma_tf32(d[mi][ni], A[mi], B[ni]);
            }
        }
    }

    // ---- epilogue: fold BN, write. d[mi][ni]: rows (m, m+8), cols (c0, c0+1)
#pragma unroll
    for (int ni = 0; ni < 4; ni++) {
        int co0 = cbase + nw * 32 + ni * 8 + kc * 2;
        int co1 = co0 + 1;
        float s0 = gam[co0] * rsqrtf(var[co0] + EPSV);
        float bi0 = bet[co0] - mu[co0] * s0;
        float s1 = gam[co1] * rsqrtf(var[co1] + EPSV);
        float bi1 = bet[co1] - mu[co1] * s1;
        size_t p0 = ((size_t)b * Ctot + Coff + co0) << 12;
        size_t p1 = ((size_t)b * Ctot + Coff + co1) << 12;
#pragma unroll
        for (int mi = 0; mi < 2; mi++) {
            int m = mw * 32 + mi * 16 + l4;
            int row = y0 + (m >> 6);
            int x = m & 63;
            size_t o = (size_t)row * 64 + x;
            out[p0 + o]     = d[mi][ni][0] * s0 + bi0;
            out[p1 + o]     = d[mi][ni][1] * s1 + bi1;
            out[p0 + o + 8] = d[mi][ni][2] * s0 + bi0;
            out[p1 + o + 8] = d[mi][ni][3] * s1 + bi1;
        }
    }
}

// ---------------------------------------------------------------------------
// conv1x1 576 -> 1 (+bias)
// ---------------------------------------------------------------------------
__global__ void conv1x1_out(const float* __restrict__ in,
                            const float* __restrict__ w,
                            const float* __restrict__ bias) {
    int x  = threadIdx.x;
    int by = blockIdx.x;
    int b  = by >> 6;
    int y  = by & 63;
    const float* p = in + (size_t)b * CMID * 4096 + y * 64 + x;
    float s0 = 0.f, s1 = 0.f, s2 = 0.f, s3 = 0.f;
#pragma unroll 4
    for (int c = 0; c < CMID; c += 4) {
        s0 += p[(c + 0) * 4096] * w[c + 0];
        s1 += p[(c + 1) * 4096] * w[c + 1];
        s2 += p[(c + 2) * 4096] * w[c + 2];
        s3 += p[(c + 3) * 4096] * w[c + 3];
    }
    g_small[(b << 12) + (y << 6) + x] = (s0 + s1) + (s2 + s3) + bias[0];
}

// ---------------------------------------------------------------------------
// bilinear x8 upsample (align_corners=True)
// ---------------------------------------------------------------------------
__global__ void upsample8(float* __restrict__ out) {
    int idx = blockIdx.x * blockDim.x + threadIdx.x;
    if (idx >= BDIM * 512 * 512) return;
    int ox = idx & 511;
    int oy = (idx >> 9) & 511;
    int b  = idx >> 18;
    const float sc = 63.0f / 511.0f;
    float fy = (float)oy * sc;
    float fx = (float)ox * sc;
    int y0 = (int)floorf(fy); int y1 = min(y0 + 1, 63);
    int x0 = (int)floorf(fx); int x1 = min(x0 + 1, 63);
    float wy = fy - (float)y0;
    float wx = fx - (float)x0;
    const float* p = g_small + (b << 12);
    float r0 = p[y0 * 64 + x0] * (1.f - wy) + p[y1 * 64 + x0] * wy;
    float r1 = p[y0 * 64 + x1] * (1.f - wy) + p[y1 * 64 + x1] * wy;
    out[idx] = r0 * (1.f - wx) + r1 * wx;
}

// ---------------------------------------------------------------------------
extern "C" void kernel_launch(void* const* d_in, const int* in_sizes, int n_in,
                              void* d_out, int out_size) {
    const float* coarse = (const float*)d_in[0];
    const float* x2     = (const float*)d_in[1];
    const float* x3     = (const float*)d_in[2];
    const float* raw    = (const float*)d_in[3];
    const float* dec_w = (const float*)d_in[6];
    const float* dec_g = (const float*)d_in[7];
    const float* dec_b = (const float*)d_in[8];
    const float* dec_m = (const float*)d_in[9];
    const float* dec_v = (const float*)d_in[10];
    const float* cc_w  = (const float*)d_in[11];
    const float* cc_g  = (const float*)d_in[12];
    const float* cc_b  = (const float*)d_in[13];
    const float* cc_m  = (const float*)d_in[14];
    const float* cc_v  = (const float*)d_in[15];
    const float* o1_w  = (const float*)d_in[16];
    const float* o1_g  = (const float*)d_in[17];
    const float* o1_b  = (const float*)d_in[18];
    const float* o1_m  = (const float*)d_in[19];
    const float* o1_v  = (const float*)d_in[20];
    const float* o2_w  = (const float*)d_in[21];
    const float* o2_b  = (const float*)d_in[22];

    float *cat1, *cat2, *mid, *mid2, *wt_dec, *wt_cc, *wt_o1;
    cudaGetSymbolAddress((void**)&cat1, g_cat1);
    cudaGetSymbolAddress((void**)&cat2, g_cat2);
    cudaGetSymbolAddress((void**)&mid,  g_mid);
    cudaGetSymbolAddress((void**)&mid2, g_mid2);
    cudaGetSymbolAddress((void**)&wt_dec, g_wt_dec);
    cudaGetSymbolAddress((void**)&wt_cc,  g_wt_cc);
    cudaGetSymbolAddress((void**)&wt_o1,  g_wt_o1);

    cudaFuncSetAttribute(conv3x3_tc,
                         cudaFuncAttributeMaxDynamicSharedMemorySize, SMEM_BYTES);

    wtrans<<<CMID * CMID / 256, 256>>>(dec_w, wt_dec, CMID * CMID);
    wtrans<<<CMID * CCAT / 256, 256>>>(cc_w,  wt_cc,  CMID * CCAT);
    wtrans<<<CMID * CMID / 256, 256>>>(o1_w,  wt_o1,  CMID * CMID);
    pack_cat1<<<(BDIM * CMID * 4096 + 255) / 256, 256>>>(coarse, raw);
    pack_sides<<<((BDIM * 768 * 4096 + BDIM * 288 * 4096) + 255) / 256, 256>>>(x2, x3);

    dim3 cgrid(128, 9);
    // dec: cat1(576) -> cat2 channels [768,1344)
    conv3x3_tc<<<cgrid, 512, SMEM_BYTES>>>(cat1, CMID, wt_dec,
        dec_g, dec_b, dec_m, dec_v, cat2, CCAT, 768);
    // cc: cat2(1632) -> mid(576)
    conv3x3_tc<<<cgrid, 512, SMEM_BYTES>>>(cat2, CCAT, wt_cc,
        cc_g, cc_b, cc_m, cc_v, mid, CMID, 0);
    // o1: mid(576) -> mid2(576)
    conv3x3_tc<<<cgrid, 512, SMEM_BYTES>>>(mid, CMID, wt_o1,
        o1_g, o1_b, o1_m, o1_v, mid2, CMID, 0);

    conv1x1_out<<<BDIM * 64, 64>>>(mid2, o2_w, o2_b);
    upsample8<<<(BDIM * 512 * 512 + 255) / 256, 256>>>((float*)d_out);
}

// round 7
// speedup vs baseline: 1.9736x; 1.9736x over previous
#include <cuda_runtime.h>
#include <math.h>
#include <stdint.h>

#define BDIM 8
#define HW 64
#define CMID 576
#define CCAT 1632
#define EPSV 1e-5f
#define NPASS 144

// conv smem geometry
#define CHUNK 8
#define HROWP 72                 // halo row pitch (floats)
#define HCSTR 440                // halo cin stride (6*72 + 8 pad) -> banks 24*kc+l4
#define HBUF  (8 * HCSTR)        // 3520 floats
#define BKPAD 152                // B n-row pitch in k... actually [pos][k][n] pitch
#define BBUF  (9 * 8 * BKPAD)    // 10944 floats
#define STAGEF (HBUF + BBUF)     // 14464 floats / stage
#define SMEM_BYTES (2 * STAGEF * 4)

// ---------------------------------------------------------------------------
// Scratch (device globals)
// ---------------------------------------------------------------------------
__device__ float g_cat1[BDIM * CMID * HW * HW];
__device__ float g_cat2[BDIM * CCAT * HW * HW];
__device__ float g_mid [BDIM * CMID * HW * HW];
__device__ float g_mid2[BDIM * CMID * HW * HW];
__device__ float g_small[BDIM * HW * HW];
__device__ float g_wt_dec[9 * CMID * CMID];
__device__ float g_wt_cc [9 * CMID * CCAT];
__device__ float g_wt_o1 [9 * CMID * CMID];

// ---------------------------------------------------------------------------
// helpers
// ---------------------------------------------------------------------------
__device__ __forceinline__ uint32_t f2tf32(float f) {
    uint32_t o;
    asm("cvt.rna.tf32.f32 %0, %1;" : "=r"(o) : "f"(f));
    return o;
}
__device__ __forceinline__ uint32_t smem_u32(const void* p) {
    uint32_t a;
    asm("{ .reg .u64 t; cvta.to.shared.u64 t, %1; cvt.u32.u64 %0, t; }" : "=r"(a) : "l"(p));
    return a;
}
__device__ __forceinline__ void mma_tf32(float* d, const uint32_t* a, const uint32_t* b) {
    asm volatile(
        "mma.sync.aligned.m16n8k8.row.col.f32.tf32.tf32.f32 "
        "{%0,%1,%2,%3}, {%4,%5,%6,%7}, {%8,%9}, {%0,%1,%2,%3};"
        : "+f"(d[0]), "+f"(d[1]), "+f"(d[2]), "+f"(d[3])
        : "r"(a[0]), "r"(a[1]), "r"(a[2]), "r"(a[3]), "r"(b[0]), "r"(b[1]));
}
__device__ __forceinline__ void cpa16(uint32_t dst, const void* src, uint32_t srcsz) {
    asm volatile("cp.async.cg.shared.global [%0], [%1], 16, %2;"
                 :: "r"(dst), "l"(src), "r"(srcsz) : "memory");
}
__device__ __forceinline__ uint32_t lds32u(uint32_t a) {
    uint32_t v;
    asm volatile("ld.shared.b32 %0, [%1];" : "=r"(v) : "r"(a));
    return v;
}
__device__ __forceinline__ void sts32(uint32_t a, float v) {
    asm volatile("st.shared.b32 [%0], %1;" :: "r"(a), "f"(v) : "memory");
}

// ---------------------------------------------------------------------------
// Weight transpose + tf32 round: OIHW [co][ci][p] -> [p][ci][co] (co contig)
// ---------------------------------------------------------------------------
__global__ void wtrans(const float* __restrict__ w, float* __restrict__ wt, int Cin) {
    int idx = blockIdx.x * 256 + threadIdx.x;
    int co = idx % CMID;
    int t  = idx / CMID;
    int ci = t % Cin;
    int pos = t / Cin;
    wt[idx] = __uint_as_float(f2tf32(w[((size_t)co * Cin + ci) * 9 + pos]));
}

// ---------------------------------------------------------------------------
// pack kernels (tf32-round at the producer)
// ---------------------------------------------------------------------------
__global__ void pack_cat1(const float* __restrict__ coarse,
                          const float* __restrict__ raw) {
    int idx = blockIdx.x * blockDim.x + threadIdx.x;
    const int N = BDIM * CMID * HW * HW;
    if (idx >= N) return;
    int x = idx & 63;
    int y = (idx >> 6) & 63;
    int c = (idx >> 12) % CMID;
    int b = idx / (CMID * HW * HW);
    float v;
    if (c < 384) {
        v = coarse[((b * 384 + c) << 12) + (y << 6) + x];
    } else {
        int pc = c - 384;
        int gy = pc / 24;
        int r  = pc - gy * 24;
        int gx = r / 3;
        int cc = r - gx * 3;
        v = raw[((b * 3 + cc) * 512 + gy * 64 + y) * 512 + gx * 64 + x];
    }
    g_cat1[idx] = __uint_as_float(f2tf32(v));
}

__global__ void pack_sides(const float* __restrict__ x2,
                           const float* __restrict__ x3) {
    int idx = blockIdx.x * blockDim.x + threadIdx.x;
    const int N2 = BDIM * 768 * HW * HW;
    const int N3 = BDIM * 288 * HW * HW;
    if (idx < N2) {
        int b = idx / (768 * 4096);
        int r = idx - b * 768 * 4096;
        g_cat2[b * CCAT * 4096 + r] = __uint_as_float(f2tf32(x2[idx]));
    } else if (idx < N2 + N3) {
        int j = idx - N2;
        int b = j / (288 * 4096);
        int r = j - b * 288 * 4096;
        g_cat2[b * CCAT * 4096 + 1344 * 4096 + r] = __uint_as_float(f2tf32(x3[j]));
    }
}

// ---------------------------------------------------------------------------
// conv3x3 + folded BN, mma.sync tf32 implicit GEMM, cp.async staging.
//   CTA: 256 thr, 8 warps (4m x 2n). Warp tile 64x72 (4 m-frags x 9 n-frags).
//   CTA tile: M=256 px (4 image rows) x N=144 couts. grid = (128, 4).
//   K loop: cin chunks of 8; double-buffered smem: halo[8][6][72-pitch] +
//   B[9][8][152-pitch]; cp.async.cg 16B, src pre-rounded to tf32.
// ---------------------------------------------------------------------------
__global__ void __launch_bounds__(256, 1)
conv3x3_tc(const float* __restrict__ in, int Cin,
           const float* __restrict__ wt,
           const float* __restrict__ gam, const float* __restrict__ bet,
           const float* __restrict__ mu,  const float* __restrict__ var,
           float* __restrict__ out, int Ctot, int Coff, int round_out) {
    extern __shared__ float sm[];
    uint32_t smb = smem_u32(sm);

    int tid = threadIdx.x;
    int wid = tid >> 5;
    int lid = tid & 31;
    int l4  = lid >> 2;
    int kc  = lid & 3;
    int mw  = wid >> 1;        // 0..3 : image row within tile
    int nw  = wid & 1;         // 0..1 : 72-cout half

    int tile = blockIdx.x;     // 128 tiles
    int b  = tile >> 4;
    int y0 = (tile & 15) << 2;
    int cbase = blockIdx.y * NPASS;

    const char* inb = (const char*)in + (size_t)b * Cin * 4096 * 4;
    const char* wtb = (const char*)wt;

    // ---- hoisted cp.async task offsets
    uint32_t hdst[3], hsrc[3], hsz[3];
#pragma unroll
    for (int i = 0; i < 3; i++) {
        int t = tid + i * 256;          // 768 tasks: 8c x 6r x 16seg
        int c = t / 96;
        int rem = t - c * 96;
        int r = rem >> 4;
        int seg = rem & 15;
        hdst[i] = (uint32_t)((c * HCSTR + r * HROWP + 4 + seg * 4) * 4);
        int yg = y0 - 1 + r;
        int ok = (yg >= 0 && yg < 64);
        hsz[i] = ok ? 16u : 0u;
        int ygc = ok ? yg : 0;
        hsrc[i] = (uint32_t)((c * 4096 + ygc * 64 + seg * 4) * 4);
    }
    uint32_t bdst[11], bsrc[11];
#pragma unroll
    for (int i = 0; i < 11; i++) {
        int t = tid + i * 256;          // 2592 tasks: 9pos x 8k x 36seg
        if (t < 2592) {
            int pos = t / 288;
            int rem = t - pos * 288;
            int k = rem / 36;
            int seg = rem - k * 36;
            bdst[i] = (uint32_t)((HBUF + (pos * 8 + k) * BKPAD + seg * 4) * 4);
            bsrc[i] = (uint32_t)((((size_t)pos * Cin + k) * CMID + cbase + seg * 4) * 4);
        } else { bdst[i] = 0; bsrc[i] = 0; }
    }

    // ---- constant-zero halo pad columns (x=-1 at idx 3, x=64 at idx 68)
    for (int e = tid; e < 192; e += 256) {
        int stg = e / 96;
        int rem = e - stg * 96;
        int c = rem / 12;
        int rem2 = rem - c * 12;
        int r = rem2 >> 1;
        int side = rem2 & 1;
        sts32(smb + (uint32_t)((stg * STAGEF + c * HCSTR + r * HROWP + (side ? 68 : 3)) * 4), 0.f);
    }

    float d[4][9][4];
#pragma unroll
    for (int mi = 0; mi < 4; mi++)
#pragma unroll
        for (int ni = 0; ni < 9; ni++)
#pragma unroll
            for (int j = 0; j < 4; j++) d[mi][ni][j] = 0.f;

    auto issue = [&](int stg) {
        uint32_t sb0 = smb + (uint32_t)stg * (STAGEF * 4);
#pragma unroll
        for (int i = 0; i < 3; i++) {
            cpa16(sb0 + hdst[i], inb + hsrc[i], hsz[i]);
            hsrc[i] += CHUNK * 4096 * 4;
        }
#pragma unroll
        for (int i = 0; i < 11; i++) {
            if (i < 10 || tid < 32) {
                cpa16(sb0 + bdst[i], wtb + bsrc[i], 16u);
                bsrc[i] += CHUNK * CMID * 4;
            }
        }
        asm volatile("cp.async.commit_group;" ::: "memory");
    };

    int nch = Cin >> 3;
    issue(0);
    for (int ch = 0; ch < nch; ch++) {
        if (ch + 1 < nch) {
            issue((ch + 1) & 1);
            asm volatile("cp.async.wait_group 1;" ::: "memory");
        } else {
            asm volatile("cp.async.wait_group 0;" ::: "memory");
        }
        __syncthreads();

        uint32_t hb = smb + (uint32_t)(ch & 1) * (STAGEF * 4);
        uint32_t bb = hb + HBUF * 4;
#pragma unroll
        for (int pos = 0; pos < 9; pos++) {
            const int ky = pos / 3, kx = pos % 3;
            uint32_t A[4][4];
#pragma unroll
            for (int mi = 0; mi < 4; mi++) {
                uint32_t a0 = hb + (uint32_t)((kc * HCSTR + (mw + ky) * HROWP +
                                               3 + kx + mi * 16 + l4) * 4);
                A[mi][0] = lds32u(a0);
                A[mi][1] = lds32u(a0 + 8 * 4);
                A[mi][2] = lds32u(a0 + 4 * HCSTR * 4);
                A[mi][3] = lds32u(a0 + (4 * HCSTR + 8) * 4);
            }
            uint32_t Bf[9][2];
#pragma unroll
            for (int ni = 0; ni < 9; ni++) {
                uint32_t b0 = bb + (uint32_t)(((pos * 8 + kc) * BKPAD +
                                               nw * 72 + ni * 8 + l4) * 4);
                Bf[ni][0] = lds32u(b0);
                Bf[ni][1] = lds32u(b0 + 4 * BKPAD * 4);
            }
#pragma unroll
            for (int mi = 0; mi < 4; mi++)
#pragma unroll
                for (int ni = 0; ni < 9; ni++)
                    mma_tf32(d[mi][ni], A[mi], Bf[ni]);
        }
        __syncthreads();
    }

    // ---- epilogue: fold BN, optional tf32 round, write
    int row = y0 + mw;
#pragma unroll
    for (int ni = 0; ni < 9; ni++) {
        int co0 = cbase + nw * 72 + ni * 8 + kc * 2;
        int co1 = co0 + 1;
        float s0 = gam[co0] * rsqrtf(var[co0] + EPSV);
        float bi0 = bet[co0] - mu[co0] * s0;
        float s1 = gam[co1] * rsqrtf(var[co1] + EPSV);
        float bi1 = bet[co1] - mu[co1] * s1;
        size_t p0 = ((size_t)b * Ctot + Coff + co0) << 12;
        size_t p1 = ((size_t)b * Ctot + Coff + co1) << 12;
#pragma unroll
        for (int mi = 0; mi < 4; mi++) {
            int x = mi * 16 + l4;
            size_t o = (size_t)row * 64 + x;
            float v0 = d[mi][ni][0] * s0 + bi0;
            float v1 = d[mi][ni][1] * s1 + bi1;
            float v2 = d[mi][ni][2] * s0 + bi0;
            float v3 = d[mi][ni][3] * s1 + bi1;
            if (round_out) {
                v0 = __uint_as_float(f2tf32(v0));
                v1 = __uint_as_float(f2tf32(v1));
                v2 = __uint_as_float(f2tf32(v2));
                v3 = __uint_as_float(f2tf32(v3));
            }
            out[p0 + o]     = v0;
            out[p1 + o]     = v1;
            out[p0 + o + 8] = v2;
            out[p1 + o + 8] = v3;
        }
    }
}

// ---------------------------------------------------------------------------
// conv1x1 576 -> 1 (+bias)
// ---------------------------------------------------------------------------
__global__ void conv1x1_out(const float* __restrict__ in,
                            const float* __restrict__ w,
                            const float* __restrict__ bias) {
    int x  = threadIdx.x;
    int by = blockIdx.x;
    int b  = by >> 6;
    int y  = by & 63;
    const float* p = in + (size_t)b * CMID * 4096 + y * 64 + x;
    float s0 = 0.f, s1 = 0.f, s2 = 0.f, s3 = 0.f;
#pragma unroll 4
    for (int c = 0; c < CMID; c += 4) {
        s0 += p[(c + 0) * 4096] * w[c + 0];
        s1 += p[(c + 1) * 4096] * w[c + 1];
        s2 += p[(c + 2) * 4096] * w[c + 2];
        s3 += p[(c + 3) * 4096] * w[c + 3];
    }
    g_small[(b << 12) + (y << 6) + x] = (s0 + s1) + (s2 + s3) + bias[0];
}

// ---------------------------------------------------------------------------
// bilinear x8 upsample (align_corners=True)
// ---------------------------------------------------------------------------
__global__ void upsample8(float* __restrict__ out) {
    int idx = blockIdx.x * blockDim.x + threadIdx.x;
    if (idx >= BDIM * 512 * 512) return;
    int ox = idx & 511;
    int oy = (idx >> 9) & 511;
    int b  = idx >> 18;
    const float sc = 63.0f / 511.0f;
    float fy = (float)oy * sc;
    float fx = (float)ox * sc;
    int y0 = (int)floorf(fy); int y1 = min(y0 + 1, 63);
    int x0 = (int)floorf(fx); int x1 = min(x0 + 1, 63);
    float wy = fy - (float)y0;
    float wx = fx - (float)x0;
    const float* p = g_small + (b << 12);
    float r0 = p[y0 * 64 + x0] * (1.f - wy) + p[y1 * 64 + x0] * wy;
    float r1 = p[y0 * 64 + x1] * (1.f - wy) + p[y1 * 64 + x1] * wy;
    out[idx] = r0 * (1.f - wx) + r1 * wx;
}

// ---------------------------------------------------------------------------
extern "C" void kernel_launch(void* const* d_in, const int* in_sizes, int n_in,
                              void* d_out, int out_size) {
    const float* coarse = (const float*)d_in[0];
    const float* x2     = (const float*)d_in[1];
    const float* x3     = (const float*)d_in[2];
    const float* raw    = (const float*)d_in[3];
    const float* dec_w = (const float*)d_in[6];
    const float* dec_g = (const float*)d_in[7];
    const float* dec_b = (const float*)d_in[8];
    const float* dec_m = (const float*)d_in[9];
    const float* dec_v = (const float*)d_in[10];
    const float* cc_w  = (const float*)d_in[11];
    const float* cc_g  = (const float*)d_in[12];
    const float* cc_b  = (const float*)d_in[13];
    const float* cc_m  = (const float*)d_in[14];
    const float* cc_v  = (const float*)d_in[15];
    const float* o1_w  = (const float*)d_in[16];
    const float* o1_g  = (const float*)d_in[17];
    const float* o1_b  = (const float*)d_in[18];
    const float* o1_m  = (const float*)d_in[19];
    const float* o1_v  = (const float*)d_in[20];
    const float* o2_w  = (const float*)d_in[21];
    const float* o2_b  = (const float*)d_in[22];

    float *cat1, *cat2, *mid, *mid2, *wt_dec, *wt_cc, *wt_o1;
    cudaGetSymbolAddress((void**)&cat1, g_cat1);
    cudaGetSymbolAddress((void**)&cat2, g_cat2);
    cudaGetSymbolAddress((void**)&mid,  g_mid);
    cudaGetSymbolAddress((void**)&mid2, g_mid2);
    cudaGetSymbolAddress((void**)&wt_dec, g_wt_dec);
    cudaGetSymbolAddress((void**)&wt_cc,  g_wt_cc);
    cudaGetSymbolAddress((void**)&wt_o1,  g_wt_o1);

    cudaFuncSetAttribute(conv3x3_tc,
                         cudaFuncAttributeMaxDynamicSharedMemorySize, SMEM_BYTES);

    wtrans<<<9 * CMID * CMID / 256, 256>>>(dec_w, wt_dec, CMID);
    wtrans<<<9 * CCAT * CMID / 256, 256>>>(cc_w,  wt_cc,  CCAT);
    wtrans<<<9 * CMID * CMID / 256, 256>>>(o1_w,  wt_o1,  CMID);
    pack_cat1<<<(BDIM * CMID * 4096 + 255) / 256, 256>>>(coarse, raw);
    pack_sides<<<((BDIM * 768 * 4096 + BDIM * 288 * 4096) + 255) / 256, 256>>>(x2, x3);

    dim3 cgrid(128, 4);
    // dec: cat1(576) -> cat2 channels [768,1344), round (feeds cc)
    conv3x3_tc<<<cgrid, 256, SMEM_BYTES>>>(cat1, CMID, wt_dec,
        dec_g, dec_b, dec_m, dec_v, cat2, CCAT, 768, 1);
    // cc: cat2(1632) -> mid(576), round (feeds o1)
    conv3x3_tc<<<cgrid, 256, SMEM_BYTES>>>(cat2, CCAT, wt_cc,
        cc_g, cc_b, cc_m, cc_v, mid, CMID, 0, 1);
    // o1: mid(576) -> mid2(576), no round (feeds fp32 conv1x1)
    conv3x3_tc<<<cgrid, 256, SMEM_BYTES>>>(mid, CMID, wt_o1,
        o1_g, o1_b, o1_m, o1_v, mid2, CMID, 0, 0);

    conv1x1_out<<<BDIM * 64, 64>>>(mid2, o2_w, o2_b);
    upsample8<<<(BDIM * 512 * 512 + 255) / 256, 256>>>((float*)d_out);
}

// round 8
// speedup vs baseline: 4.0848x; 2.0697x over previous
#include <cuda_runtime.h>
#include <cuda_fp16.h>
#include <math.h>
#include <stdint.h>

#define BDIM 8
#define HW 64
#define CMID 576
#define CCAT 1632
#define EPSV 1e-5f
#define NPASS 144

// conv smem geometry (fp16, chunk of 16 cin)
#define HALO_B (6 * 66 * 16 * 2)        // 12672 B
#define BT_B   (9 * 144 * 16 * 2)       // 41472 B
#define STG_B  (HALO_B + BT_B)          // 54144 B
#define NSTG   3
#define SMEM_BYTES (NSTG * STG_B)       // 162432 B

#define E1 2985984                       // 36*9*576*16 (dec/o1 wt elems)
#define E2 8460288                       // 102*9*576*16 (cc wt elems)

// ---------------------------------------------------------------------------
// Scratch (device globals)
// ---------------------------------------------------------------------------
__device__ __half g_cat1h[BDIM * 36 * 4096 * 16];
__device__ __half g_cat2h[BDIM * 102 * 4096 * 16];
__device__ __half g_midh [BDIM * 36 * 4096 * 16];
__device__ float  g_mid2 [BDIM * CMID * 4096];
__device__ float  g_small[BDIM * 4096];
__device__ __half g_wdh[E1];
__device__ __half g_wch[E2];
__device__ __half g_woh[E1];

// ---------------------------------------------------------------------------
// helpers
// ---------------------------------------------------------------------------
__device__ __forceinline__ uint32_t smem_u32(const void* p) {
    uint32_t a;
    asm("{ .reg .u64 t; cvta.to.shared.u64 t, %1; cvt.u32.u64 %0, t; }" : "=r"(a) : "l"(p));
    return a;
}
__device__ __forceinline__ void ldm_x4(uint32_t* r, uint32_t a) {
    asm volatile("ldmatrix.sync.aligned.m8n8.x4.shared.b16 {%0,%1,%2,%3}, [%4];"
                 : "=r"(r[0]), "=r"(r[1]), "=r"(r[2]), "=r"(r[3]) : "r"(a));
}
__device__ __forceinline__ void ldm_x2(uint32_t* r, uint32_t a) {
    asm volatile("ldmatrix.sync.aligned.m8n8.x2.shared.b16 {%0,%1}, [%2];"
                 : "=r"(r[0]), "=r"(r[1]) : "r"(a));
}
__device__ __forceinline__ void mma_f16(float* d, const uint32_t* a, uint32_t b0, uint32_t b1) {
    asm volatile("mma.sync.aligned.m16n8k16.row.col.f32.f16.f16.f32 "
        "{%0,%1,%2,%3}, {%4,%5,%6,%7}, {%8,%9}, {%0,%1,%2,%3};"
        : "+f"(d[0]), "+f"(d[1]), "+f"(d[2]), "+f"(d[3])
        : "r"(a[0]), "r"(a[1]), "r"(a[2]), "r"(a[3]), "r"(b0), "r"(b1));
}
__device__ __forceinline__ void cpa16(uint32_t dst, const void* src, uint32_t srcsz) {
    asm volatile("cp.async.cg.shared.global [%0], [%1], 16, %2;"
                 :: "r"(dst), "l"(src), "r"(srcsz) : "memory");
}
__device__ __forceinline__ void sts32z(uint32_t a) {
    asm volatile("st.shared.b32 [%0], %1;" :: "r"(a), "r"(0u) : "memory");
}

// ---------------------------------------------------------------------------
// Weight transform (all 3 convs in one launch):
// OIHW fp32 -> fp16 [ci-chunk16][pos][co][kl16]
// ---------------------------------------------------------------------------
__global__ void wtrans_all(const float* __restrict__ wd, const float* __restrict__ wc,
                           const float* __restrict__ wo,
                           __half* __restrict__ td, __half* __restrict__ tc,
                           __half* __restrict__ to) {
    size_t idx = (size_t)blockIdx.x * 256 + threadIdx.x;
    const float* src; __half* dst; int Cin; size_t loc;
    if (idx < E1)            { src = wd; dst = td; Cin = 576;  loc = idx; }
    else if (idx < E1 + E2)  { src = wc; dst = tc; Cin = 1632; loc = idx - E1; }
    else                     { src = wo; dst = to; Cin = 576;  loc = idx - E1 - E2; }
    int kl = (int)(loc & 15);
    size_t t = loc >> 4;
    int co = (int)(t % 576); t /= 576;
    int pos = (int)(t % 9);
    int ch = (int)(t / 9);
    int ci = ch * 16 + kl;
    dst[loc] = __float2half_rn(src[((size_t)co * Cin + ci) * 9 + pos]);
}

// ---------------------------------------------------------------------------
// pack_all: build cat1h (36 chunks: coarse 0-23 + raw patches 24-35) and
// cat2h side chunks (x2 -> 0-47, x3 -> 84-101), fp16 chunk-16 layout.
// One block per (b, chunk, y).
// ---------------------------------------------------------------------------
__global__ void __launch_bounds__(256)
pack_all(const float* __restrict__ coarse, const float* __restrict__ x2,
         const float* __restrict__ x3, const float* __restrict__ raw,
         __half* __restrict__ cat1h, __half* __restrict__ cat2h) {
    __shared__ float sb[16][65];
    int id = blockIdx.x;
    int y = id & 63;
    int t = id >> 6;
    int ch = t % 102;
    int b = t / 102;
    int tid = threadIdx.x;

#pragma unroll
    for (int k = 0; k < 4; k++) {
        int e = tid + k * 256;
        int cl = e >> 6;
        int x = e & 63;
        float v;
        if (ch < 36) {
            int c = ch * 16 + cl;
            if (c < 384) {
                v = coarse[((b * 384 + c) << 12) + (y << 6) + x];
            } else {
                int pc = c - 384;
                int gy = pc / 24;
                int r  = pc - gy * 24;
                int gx = r / 3;
                int cc = r - gx * 3;
                v = raw[((b * 3 + cc) * 512 + gy * 64 + y) * 512 + gx * 64 + x];
            }
        } else if (ch < 84) {
            int c = (ch - 36) * 16 + cl;
            v = x2[((b * 768 + c) << 12) + (y << 6) + x];
        } else {
            int c = (ch - 84) * 16 + cl;
            v = x3[((b * 288 + c) << 12) + (y << 6) + x];
        }
        sb[cl][x] = v;
    }
    __syncthreads();

    __half* dstp;
    size_t base;
    if (ch < 36) {
        dstp = cat1h;
        base = (((size_t)(b * 36 + ch)) * 4096 + y * 64) * 16;
    } else {
        int c2 = (ch < 84) ? (ch - 36) : ch;   // x2 -> 0..47, x3 -> 84..101
        dstp = cat2h;
        base = (((size_t)(b * 102 + c2)) * 4096 + y * 64) * 16;
    }
#pragma unroll
    for (int k = 0; k < 2; k++) {
        int w = tid + k * 256;
        int j0 = 2 * w;
        int cl = j0 & 15;
        int x = j0 >> 4;
        *(__half2*)(dstp + base + j0) = __floats2half2_rn(sb[cl][x], sb[cl + 1][x]);
    }
}

// ---------------------------------------------------------------------------
// conv3x3 + folded BN: fp16 mma.m16n8k16 implicit GEMM, ldmatrix fragments.
//   CTA 256 thr, 8 warps (4m x 2n); warp tile 64px x 72co; CTA M=256 N=144.
//   K loop: cin chunks of 16 (one k16 mma step per pos). 3-stage cp.async.
//   Input fp16 [b][ch][y][x][16]; weights fp16 [ch][pos][co][k16].
//   Output: fp16 chunk layout (outh) or fp32 planar (outf, for conv1x1).
// ---------------------------------------------------------------------------
__global__ void __launch_bounds__(256)
conv3x3_h(const __half* __restrict__ in, int Cin,
          const __half* __restrict__ wt,
          const float* __restrict__ gam, const float* __restrict__ bet,
          const float* __restrict__ mu,  const float* __restrict__ var,
          __half* __restrict__ outh, int CHT, int och_off,
          float* __restrict__ outf) {
    extern __shared__ char smc[];
    uint32_t smb = smem_u32(smc);

    int tid = threadIdx.x;
    int wid = tid >> 5;
    int lid = tid & 31;
    int l4 = lid >> 2;
    int kc = lid & 3;
    int mw = wid >> 1;
    int nw = wid & 1;

    int tile = blockIdx.x;
    int b  = tile >> 4;
    int y0 = (tile & 15) << 2;
    int cbase = blockIdx.y * NPASS;

    const char* inb = (const char*)(in + (size_t)b * Cin * 4096);
    const char* wtb = (const char*)wt;

    // hoisted halo tasks: 768 = 6row x 64x x 2seg
    uint32_t hdst[3], hsrc[3], hsz[3];
#pragma unroll
    for (int i = 0; i < 3; i++) {
        int t = tid + i * 256;
        int row = t >> 7;
        int rem = t & 127;
        int x = rem >> 1;
        int seg = rem & 1;
        hdst[i] = (uint32_t)(((row * 66 + 1 + x) * 16 + seg * 8) * 2);
        int yg = y0 - 1 + row;
        int ok = (yg >= 0 && yg < 64);
        hsz[i] = ok ? 16u : 0u;
        hsrc[i] = (uint32_t)((((ok ? yg : 0) * 64 + x) * 16 + seg * 8) * 2);
    }
    // hoisted B tasks: 2592 = 9pos x 144n x 2seg
    uint32_t bdst[11], bsrc[11];
#pragma unroll
    for (int i = 0; i < 11; i++) {
        int t = tid + i * 256;
        if (t < 2592) {
            int pos = t / 288;
            int rem = t - pos * 288;
            int n = rem >> 1;
            int seg = rem & 1;
            bdst[i] = (uint32_t)(HALO_B + ((pos * 144 + n) * 16 + seg * 8) * 2);
            bsrc[i] = (uint32_t)((((pos * 576) + cbase + n) * 16 + seg * 8) * 2);
        } else { bdst[i] = 0; bsrc[i] = 0; }
    }

    // zero halo pad columns (xx = 0 and 65) in all stages
    for (int e = tid; e < 288; e += 256) {
        int stg = e / 96;
        int rem = e - stg * 96;
        int row = rem >> 4;
        int rem2 = rem & 15;
        int side = rem2 >> 3;
        int w = rem2 & 7;
        sts32z(smb + (uint32_t)(stg * STG_B + ((row * 66 + (side ? 65 : 0)) * 16) * 2 + w * 4));
    }

    float d[4][9][4];
#pragma unroll
    for (int mi = 0; mi < 4; mi++)
#pragma unroll
        for (int ni = 0; ni < 9; ni++)
#pragma unroll
            for (int j = 0; j < 4; j++) d[mi][ni][j] = 0.f;

    auto issue = [&](int buf) {
        uint32_t sb0 = smb + (uint32_t)buf * STG_B;
#pragma unroll
        for (int i = 0; i < 3; i++) {
            cpa16(sb0 + hdst[i], inb + hsrc[i], hsz[i]);
            hsrc[i] += 4096u * 16u * 2u;
        }
#pragma unroll
        for (int i = 0; i < 11; i++) {
            if (i < 10 || tid < 32) {
                cpa16(sb0 + bdst[i], wtb + bsrc[i], 16u);
                bsrc[i] += 9u * 576u * 16u * 2u;
            }
        }
        asm volatile("cp.async.commit_group;" ::: "memory");
    };

    // lane-derived ldmatrix offsets
    uint32_t xoffA = (uint32_t)((lid & 7) + (lid & 8));
    uint32_t khA   = (uint32_t)((lid >> 4) * 16);
    uint32_t noffB = (uint32_t)((lid & 7) + ((lid & 16) >> 1));
    uint32_t khB   = (uint32_t)(((lid >> 3) & 1) * 16);

    int nch = Cin >> 4;
    issue(0);
    issue(1 % NSTG);
    for (int ch = 0; ch < nch; ch++) {
        asm volatile("cp.async.wait_group 1;" ::: "memory");
        __syncthreads();

        uint32_t hb = smb + (uint32_t)(ch % NSTG) * STG_B;
        uint32_t bb = hb + HALO_B;
#pragma unroll
        for (int pos = 0; pos < 9; pos++) {
            const int ky = pos / 3, kx = pos % 3;
            uint32_t A[4][4];
            uint32_t pa = hb + (uint32_t)(((mw + ky) * 66 + kx) * 32) + xoffA * 32 + khA;
#pragma unroll
            for (int mi = 0; mi < 4; mi++)
                ldm_x4(A[mi], pa + (uint32_t)mi * 512);

            uint32_t pb = bb + (uint32_t)(pos * 4608) + (uint32_t)(nw * 72) * 32 + noffB * 32 + khB;
#pragma unroll
            for (int pp = 0; pp < 4; pp++) {
                uint32_t Bv[4];
                ldm_x4(Bv, pb + (uint32_t)pp * 512);
#pragma unroll
                for (int mi = 0; mi < 4; mi++) {
                    mma_f16(d[mi][2 * pp],     A[mi], Bv[0], Bv[1]);
                    mma_f16(d[mi][2 * pp + 1], A[mi], Bv[2], Bv[3]);
                }
            }
            {
                uint32_t pb8 = bb + (uint32_t)(pos * 4608) +
                               (uint32_t)((nw * 72 + 64 + (lid & 7)) * 32) + khB;
                uint32_t Bv[2];
                ldm_x2(Bv, pb8);
#pragma unroll
                for (int mi = 0; mi < 4; mi++)
                    mma_f16(d[mi][8], A[mi], Bv[0], Bv[1]);
            }
        }
        if (ch + 2 < nch) issue((ch + 2) % NSTG);
    }

    // ---- epilogue
    int row = y0 + mw;
#pragma unroll
    for (int ni = 0; ni < 9; ni++) {
        int col = nw * 72 + ni * 8 + kc * 2;
        int co0 = cbase + col;
        int co1 = co0 + 1;
        float s0 = gam[co0] * rsqrtf(var[co0] + EPSV);
        float bi0 = bet[co0] - mu[co0] * s0;
        float s1 = gam[co1] * rsqrtf(var[co1] + EPSV);
        float bi1 = bet[co1] - mu[co1] * s1;
        if (outf) {
            size_t p0 = ((size_t)b * CMID + co0) << 12;
            size_t p1 = ((size_t)b * CMID + co1) << 12;
#pragma unroll
            for (int mi = 0; mi < 4; mi++) {
                int x = mi * 16 + l4;
                size_t o = (size_t)row * 64 + x;
                outf[p0 + o]     = d[mi][ni][0] * s0 + bi0;
                outf[p1 + o]     = d[mi][ni][1] * s1 + bi1;
                outf[p0 + o + 8] = d[mi][ni][2] * s0 + bi0;
                outf[p1 + o + 8] = d[mi][ni][3] * s1 + bi1;
            }
        } else {
            int chn = (co0 >> 4) + och_off;
            int cl = co0 & 15;
            size_t basei = (((size_t)b * CHT + chn) * 4096 + row * 64) * 16 + cl;
#pragma unroll
            for (int mi = 0; mi < 4; mi++) {
                int x = mi * 16 + l4;
                *(__half2*)(outh + basei + (size_t)x * 16) =
                    __floats2half2_rn(d[mi][ni][0] * s0 + bi0, d[mi][ni][1] * s1 + bi1);
                *(__half2*)(outh + basei + (size_t)(x + 8) * 16) =
                    __floats2half2_rn(d[mi][ni][2] * s0 + bi0, d[mi][ni][3] * s1 + bi1);
            }
        }
    }
}

// ---------------------------------------------------------------------------
// conv1x1 576 -> 1 (+bias), fp32 planar input
// ---------------------------------------------------------------------------
__global__ void conv1x1_out(const float* __restrict__ in,
                            const float* __restrict__ w,
                            const float* __restrict__ bias) {
    int x  = threadIdx.x;
    int by = blockIdx.x;
    int b  = by >> 6;
    int y  = by & 63;
    const float* p = in + (size_t)b * CMID * 4096 + y * 64 + x;
    float s0 = 0.f, s1 = 0.f, s2 = 0.f, s3 = 0.f;
#pragma unroll 4
    for (int c = 0; c < CMID; c += 4) {
        s0 += p[(c + 0) * 4096] * w[c + 0];
        s1 += p[(c + 1) * 4096] * w[c + 1];
        s2 += p[(c + 2) * 4096] * w[c + 2];
        s3 += p[(c + 3) * 4096] * w[c + 3];
    }
    g_small[(b << 12) + (y << 6) + x] = (s0 + s1) + (s2 + s3) + bias[0];
}

// ---------------------------------------------------------------------------
// bilinear x8 upsample (align_corners=True)
// ---------------------------------------------------------------------------
__global__ void upsample8(float* __restrict__ out) {
    int idx = blockIdx.x * blockDim.x + threadIdx.x;
    if (idx >= BDIM * 512 * 512) return;
    int ox = idx & 511;
    int oy = (idx >> 9) & 511;
    int b  = idx >> 18;
    const float sc = 63.0f / 511.0f;
    float fy = (float)oy * sc;
    float fx = (float)ox * sc;
    int y0 = (int)floorf(fy); int y1 = min(y0 + 1, 63);
    int x0 = (int)floorf(fx); int x1 = min(x0 + 1, 63);
    float wy = fy - (float)y0;
    float wx = fx - (float)x0;
    const float* p = g_small + (b << 12);
    float r0 = p[y0 * 64 + x0] * (1.f - wy) + p[y1 * 64 + x0] * wy;
    float r1 = p[y0 * 64 + x1] * (1.f - wy) + p[y1 * 64 + x1] * wy;
    out[idx] = r0 * (1.f - wx) + r1 * wx;
}

// ---------------------------------------------------------------------------
extern "C" void kernel_launch(void* const* d_in, const int* in_sizes, int n_in,
                              void* d_out, int out_size) {
    const float* coarse = (const float*)d_in[0];
    const float* x2     = (const float*)d_in[1];
    const float* x3     = (const float*)d_in[2];
    const float* raw    = (const float*)d_in[3];
    const float* dec_w = (const float*)d_in[6];
    const float* dec_g = (const float*)d_in[7];
    const float* dec_b = (const float*)d_in[8];
    const float* dec_m = (const float*)d_in[9];
    const float* dec_v = (const float*)d_in[10];
    const float* cc_w  = (const float*)d_in[11];
    const float* cc_g  = (const float*)d_in[12];
    const float* cc_b  = (const float*)d_in[13];
    const float* cc_m  = (const float*)d_in[14];
    const float* cc_v  = (const float*)d_in[15];
    const float* o1_w  = (const float*)d_in[16];
    const float* o1_g  = (const float*)d_in[17];
    const float* o1_b  = (const float*)d_in[18];
    const float* o1_m  = (const float*)d_in[19];
    const float* o1_v  = (const float*)d_in[20];
    const float* o2_w  = (const float*)d_in[21];
    const float* o2_b  = (const float*)d_in[22];

    __half *cat1h, *cat2h, *midh, *wdh, *wch, *woh;
    float *mid2;
    cudaGetSymbolAddress((void**)&cat1h, g_cat1h);
    cudaGetSymbolAddress((void**)&cat2h, g_cat2h);
    cudaGetSymbolAddress((void**)&midh,  g_midh);
    cudaGetSymbolAddress((void**)&mid2,  g_mid2);
    cudaGetSymbolAddress((void**)&wdh, g_wdh);
    cudaGetSymbolAddress((void**)&wch, g_wch);
    cudaGetSymbolAddress((void**)&woh, g_woh);

    cudaFuncSetAttribute(conv3x3_h,
                         cudaFuncAttributeMaxDynamicSharedMemorySize, SMEM_BYTES);

    // launch 0: all weight transforms
    wtrans_all<<<(E1 + E2 + E1) / 256, 256>>>(dec_w, cc_w, o1_w, wdh, wch, woh);
    // launch 1: all input packing
    pack_all<<<BDIM * 102 * 64, 256>>>(coarse, x2, x3, raw, cat1h, cat2h);

    dim3 cgrid(128, 4);
    // launch 2: dec  cat1h(576) -> cat2h chunks [48,84)
    conv3x3_h<<<cgrid, 256, SMEM_BYTES>>>(cat1h, CMID, wdh,
        dec_g, dec_b, dec_m, dec_v, cat2h, 102, 48, nullptr);
    // launch 3: cc   cat2h(1632) -> midh
    conv3x3_h<<<cgrid, 256, SMEM_BYTES>>>(cat2h, CCAT, wch,
        cc_g, cc_b, cc_m, cc_v, midh, 36, 0, nullptr);
    // launch 4: o1   midh(576) -> mid2 (fp32 planar)
    conv3x3_h<<<cgrid, 256, SMEM_BYTES>>>(midh, CMID, woh,
        o1_g, o1_b, o1_m, o1_v, nullptr, 0, 0, mid2);

    conv1x1_out<<<BDIM * 64, 64>>>(mid2, o2_w, o2_b);
    upsample8<<<(BDIM * 512 * 512 + 255) / 256, 256>>>((float*)d_out);
}

// round 9
// speedup vs baseline: 4.1541x; 1.0170x over previous
#include <cuda_runtime.h>
#include <cuda_fp16.h>
#include <math.h>
#include <stdint.h>

#define BDIM 8
#define HW 64
#define CMID 576
#define CCAT 1632
#define EPSV 1e-5f
#define NPASS 144

// conv smem geometry (fp16, chunk of 16 cin)
#define HALO_B (6 * 66 * 16 * 2)        // 12672 B
#define BT_B   (9 * 144 * 16 * 2)       // 41472 B
#define STG_B  (HALO_B + BT_B)          // 54144 B
#define NSTG   3
#define SMEM_BYTES (NSTG * STG_B)       // 162432 B

#define E1 2985984                       // 36*9*576*16 (dec/o1 wt elems)
#define E2 8460288                       // 102*9*576*16 (cc wt elems)
#define WT_SMEM (14688 * 4)              // cc row: 1632*9 floats

// ---------------------------------------------------------------------------
// Scratch (device globals)
// ---------------------------------------------------------------------------
__device__ __half g_cat1h[BDIM * 36 * 4096 * 16];
__device__ __half g_cat2h[BDIM * 102 * 4096 * 16];
__device__ __half g_midh [BDIM * 36 * 4096 * 16];
__device__ float  g_part [4 * BDIM * 4096];
__device__ float  g_small[BDIM * 4096];
__device__ __half g_wdh[E1];
__device__ __half g_wch[E2];
__device__ __half g_woh[E1];

// ---------------------------------------------------------------------------
// helpers
// ---------------------------------------------------------------------------
__device__ __forceinline__ uint32_t smem_u32(const void* p) {
    uint32_t a;
    asm("{ .reg .u64 t; cvta.to.shared.u64 t, %1; cvt.u32.u64 %0, t; }" : "=r"(a) : "l"(p));
    return a;
}
__device__ __forceinline__ void ldm_x4(uint32_t* r, uint32_t a) {
    asm volatile("ldmatrix.sync.aligned.m8n8.x4.shared.b16 {%0,%1,%2,%3}, [%4];"
                 : "=r"(r[0]), "=r"(r[1]), "=r"(r[2]), "=r"(r[3]) : "r"(a));
}
__device__ __forceinline__ void ldm_x2(uint32_t* r, uint32_t a) {
    asm volatile("ldmatrix.sync.aligned.m8n8.x2.shared.b16 {%0,%1}, [%2];"
                 : "=r"(r[0]), "=r"(r[1]) : "r"(a));
}
__device__ __forceinline__ void mma_f16(float* d, const uint32_t* a, uint32_t b0, uint32_t b1) {
    asm volatile("mma.sync.aligned.m16n8k16.row.col.f32.f16.f16.f32 "
        "{%0,%1,%2,%3}, {%4,%5,%6,%7}, {%8,%9}, {%0,%1,%2,%3};"
        : "+f"(d[0]), "+f"(d[1]), "+f"(d[2]), "+f"(d[3])
        : "r"(a[0]), "r"(a[1]), "r"(a[2]), "r"(a[3]), "r"(b0), "r"(b1));
}
__device__ __forceinline__ void cpa16(uint32_t dst, const void* src, uint32_t srcsz) {
    asm volatile("cp.async.cg.shared.global [%0], [%1], 16, %2;"
                 :: "r"(dst), "l"(src), "r"(srcsz) : "memory");
}
__device__ __forceinline__ void sts32z(uint32_t a) {
    asm volatile("st.shared.b32 [%0], %1;" :: "r"(a), "r"(0u) : "memory");
}

// ---------------------------------------------------------------------------
// Coalesced weight transform: one block per (conv, cout).
// Stage the contiguous Cin*9 fp32 row in smem, emit [ch][pos][co][kl16] fp16.
// ---------------------------------------------------------------------------
__global__ void __launch_bounds__(256)
wtrans2(const float* __restrict__ wd, const float* __restrict__ wc,
        const float* __restrict__ wo,
        __half* __restrict__ td, __half* __restrict__ tc, __half* __restrict__ to) {
    extern __shared__ float s[];
    int co = blockIdx.x % CMID;
    int conv = blockIdx.x / CMID;
    const float* src; __half* dst; int Cin;
    if (conv == 0)      { src = wd; dst = td; Cin = 576; }
    else if (conv == 1) { src = wc; dst = tc; Cin = 1632; }
    else                { src = wo; dst = to; Cin = 576; }
    int n = Cin * 9;
    const float* row = src + (size_t)co * n;
    int tid = threadIdx.x;
    for (int i = tid; i < n; i += 256) s[i] = row[i];
    __syncthreads();
    int nu = (Cin >> 4) * 9;
    for (int u = tid; u < nu; u += 256) {
        int ch = u / 9;
        int pos = u - ch * 9;
        __half2* dp = (__half2*)(dst + ((size_t)u * CMID + co) * 16);
#pragma unroll
        for (int k2 = 0; k2 < 8; k2++) {
            float a = s[(ch * 16 + 2 * k2) * 9 + pos];
            float b = s[(ch * 16 + 2 * k2 + 1) * 9 + pos];
            dp[k2] = __floats2half2_rn(a, b);
        }
    }
}

// ---------------------------------------------------------------------------
// pack_all: build cat1h (36 chunks) and cat2h side chunks, fp16 chunk-16.
// ---------------------------------------------------------------------------
__global__ void __launch_bounds__(256)
pack_all(const float* __restrict__ coarse, const float* __restrict__ x2,
         const float* __restrict__ x3, const float* __restrict__ raw,
         __half* __restrict__ cat1h, __half* __restrict__ cat2h) {
    __shared__ float sb[16][65];
    int id = blockIdx.x;
    int y = id & 63;
    int t = id >> 6;
    int ch = t % 102;
    int b = t / 102;
    int tid = threadIdx.x;

#pragma unroll
    for (int k = 0; k < 4; k++) {
        int e = tid + k * 256;
        int cl = e >> 6;
        int x = e & 63;
        float v;
        if (ch < 36) {
            int c = ch * 16 + cl;
            if (c < 384) {
                v = coarse[((b * 384 + c) << 12) + (y << 6) + x];
            } else {
                int pc = c - 384;
                int gy = pc / 24;
                int r  = pc - gy * 24;
                int gx = r / 3;
                int cc = r - gx * 3;
                v = raw[((b * 3 + cc) * 512 + gy * 64 + y) * 512 + gx * 64 + x];
            }
        } else if (ch < 84) {
            int c = (ch - 36) * 16 + cl;
            v = x2[((b * 768 + c) << 12) + (y << 6) + x];
        } else {
            int c = (ch - 84) * 16 + cl;
            v = x3[((b * 288 + c) << 12) + (y << 6) + x];
        }
        sb[cl][x] = v;
    }
    __syncthreads();

    __half* dstp;
    size_t base;
    if (ch < 36) {
        dstp = cat1h;
        base = (((size_t)(b * 36 + ch)) * 4096 + y * 64) * 16;
    } else {
        int c2 = (ch < 84) ? (ch - 36) : ch;
        dstp = cat2h;
        base = (((size_t)(b * 102 + c2)) * 4096 + y * 64) * 16;
    }
#pragma unroll
    for (int k = 0; k < 2; k++) {
        int w = tid + k * 256;
        int j0 = 2 * w;
        int cl = j0 & 15;
        int x = j0 >> 4;
        *(__half2*)(dstp + base + j0) = __floats2half2_rn(sb[cl][x], sb[cl + 1][x]);
    }
}

// ---------------------------------------------------------------------------
// conv3x3 + folded BN, fp16 mma.m16n8k16 implicit GEMM.
//   outh != null : fp16 chunk-layout output (dec, cc)
//   outh == null : fused conv1x1 epilogue — BN, dot with w2, CTA-reduce,
//                  per-pass partial to part[] (o1)
// ---------------------------------------------------------------------------
__global__ void __launch_bounds__(256)
conv3x3_h(const __half* __restrict__ in, int Cin,
          const __half* __restrict__ wt,
          const float* __restrict__ gam, const float* __restrict__ bet,
          const float* __restrict__ mu,  const float* __restrict__ var,
          __half* __restrict__ outh, int CHT, int och_off,
          const float* __restrict__ w2, float* __restrict__ part) {
    extern __shared__ char smc[];
    __shared__ float red[2][4][64];
    uint32_t smb = smem_u32(smc);

    int tid = threadIdx.x;
    int wid = tid >> 5;
    int lid = tid & 31;
    int l4 = lid >> 2;
    int kc = lid & 3;
    int mw = wid >> 1;
    int nw = wid & 1;

    int tile = blockIdx.x;
    int b  = tile >> 4;
    int y0 = (tile & 15) << 2;
    int pass = blockIdx.y;
    int cbase = pass * NPASS;

    const char* inb = (const char*)(in + (size_t)b * Cin * 4096);
    const char* wtb = (const char*)wt;

    uint32_t hdst[3], hsrc[3], hsz[3];
#pragma unroll
    for (int i = 0; i < 3; i++) {
        int t = tid + i * 256;
        int row = t >> 7;
        int rem = t & 127;
        int x = rem >> 1;
        int seg = rem & 1;
        hdst[i] = (uint32_t)(((row * 66 + 1 + x) * 16 + seg * 8) * 2);
        int yg = y0 - 1 + row;
        int ok = (yg >= 0 && yg < 64);
        hsz[i] = ok ? 16u : 0u;
        hsrc[i] = (uint32_t)((((ok ? yg : 0) * 64 + x) * 16 + seg * 8) * 2);
    }
    uint32_t bdst[11], bsrc[11];
#pragma unroll
    for (int i = 0; i < 11; i++) {
        int t = tid + i * 256;
        if (t < 2592) {
            int pos = t / 288;
            int rem = t - pos * 288;
            int n = rem >> 1;
            int seg = rem & 1;
            bdst[i] = (uint32_t)(HALO_B + ((pos * 144 + n) * 16 + seg * 8) * 2);
            bsrc[i] = (uint32_t)((((pos * 576) + cbase + n) * 16 + seg * 8) * 2);
        } else { bdst[i] = 0; bsrc[i] = 0; }
    }

    for (int e = tid; e < 288; e += 256) {
        int stg = e / 96;
        int rem = e - stg * 96;
        int row = rem >> 4;
        int rem2 = rem & 15;
        int side = rem2 >> 3;
        int w = rem2 & 7;
        sts32z(smb + (uint32_t)(stg * STG_B + ((row * 66 + (side ? 65 : 0)) * 16) * 2 + w * 4));
    }

    float d[4][9][4];
#pragma unroll
    for (int mi = 0; mi < 4; mi++)
#pragma unroll
        for (int ni = 0; ni < 9; ni++)
#pragma unroll
            for (int j = 0; j < 4; j++) d[mi][ni][j] = 0.f;

    auto issue = [&](int buf) {
        uint32_t sb0 = smb + (uint32_t)buf * STG_B;
#pragma unroll
        for (int i = 0; i < 3; i++) {
            cpa16(sb0 + hdst[i], inb + hsrc[i], hsz[i]);
            hsrc[i] += 4096u * 16u * 2u;
        }
#pragma unroll
        for (int i = 0; i < 11; i++) {
            if (i < 10 || tid < 32) {
                cpa16(sb0 + bdst[i], wtb + bsrc[i], 16u);
                bsrc[i] += 9u * 576u * 16u * 2u;
            }
        }
        asm volatile("cp.async.commit_group;" ::: "memory");
    };

    uint32_t xoffA = (uint32_t)((lid & 7) + (lid & 8));
    uint32_t khA   = (uint32_t)((lid >> 4) * 16);
    uint32_t noffB = (uint32_t)((lid & 7) + ((lid & 16) >> 1));
    uint32_t khB   = (uint32_t)(((lid >> 3) & 1) * 16);

    int nch = Cin >> 4;
    issue(0);
    issue(1 % NSTG);
    for (int ch = 0; ch < nch; ch++) {
        asm volatile("cp.async.wait_group 1;" ::: "memory");
        __syncthreads();

        uint32_t hb = smb + (uint32_t)(ch % NSTG) * STG_B;
        uint32_t bb = hb + HALO_B;
#pragma unroll
        for (int pos = 0; pos < 9; pos++) {
            const int ky = pos / 3, kx = pos % 3;
            uint32_t A[4][4];
            uint32_t pa = hb + (uint32_t)(((mw + ky) * 66 + kx) * 32) + xoffA * 32 + khA;
#pragma unroll
            for (int mi = 0; mi < 4; mi++)
                ldm_x4(A[mi], pa + (uint32_t)mi * 512);

            uint32_t pb = bb + (uint32_t)(pos * 4608) + (uint32_t)(nw * 72) * 32 + noffB * 32 + khB;
#pragma unroll
            for (int pp = 0; pp < 4; pp++) {
                uint32_t Bv[4];
                ldm_x4(Bv, pb + (uint32_t)pp * 512);
#pragma unroll
                for (int mi = 0; mi < 4; mi++) {
                    mma_f16(d[mi][2 * pp],     A[mi], Bv[0], Bv[1]);
                    mma_f16(d[mi][2 * pp + 1], A[mi], Bv[2], Bv[3]);
                }
            }
            {
                uint32_t pb8 = bb + (uint32_t)(pos * 4608) +
                               (uint32_t)((nw * 72 + 64 + (lid & 7)) * 32) + khB;
                uint32_t Bv[2];
                ldm_x2(Bv, pb8);
#pragma unroll
                for (int mi = 0; mi < 4; mi++)
                    mma_f16(d[mi][8], A[mi], Bv[0], Bv[1]);
            }
        }
        if (ch + 2 < nch) issue((ch + 2) % NSTG);
    }

    int row = y0 + mw;
    if (outh) {
        // ---- fp16 chunk-layout epilogue (dec, cc)
#pragma unroll
        for (int ni = 0; ni < 9; ni++) {
            int co0 = cbase + nw * 72 + ni * 8 + kc * 2;
            int co1 = co0 + 1;
            float s0 = gam[co0] * rsqrtf(var[co0] + EPSV);
            float bi0 = bet[co0] - mu[co0] * s0;
            float s1 = gam[co1] * rsqrtf(var[co1] + EPSV);
            float bi1 = bet[co1] - mu[co1] * s1;
            int chn = (co0 >> 4) + och_off;
            int cl = co0 & 15;
            size_t basei = (((size_t)b * CHT + chn) * 4096 + row * 64) * 16 + cl;
#pragma unroll
            for (int mi = 0; mi < 4; mi++) {
                int x = mi * 16 + l4;
                *(__half2*)(outh + basei + (size_t)x * 16) =
                    __floats2half2_rn(d[mi][ni][0] * s0 + bi0, d[mi][ni][1] * s1 + bi1);
                *(__half2*)(outh + basei + (size_t)(x + 8) * 16) =
                    __floats2half2_rn(d[mi][ni][2] * s0 + bi0, d[mi][ni][3] * s1 + bi1);
            }
        }
    } else {
        // ---- fused conv1x1 epilogue (o1): BN -> dot w2 -> CTA reduce
        float pa[4], pb[4];
#pragma unroll
        for (int mi = 0; mi < 4; mi++) { pa[mi] = 0.f; pb[mi] = 0.f; }
#pragma unroll
        for (int ni = 0; ni < 9; ni++) {
            int co0 = cbase + nw * 72 + ni * 8 + kc * 2;
            int co1 = co0 + 1;
            float s0 = gam[co0] * rsqrtf(var[co0] + EPSV);
            float bi0 = bet[co0] - mu[co0] * s0;
            float s1 = gam[co1] * rsqrtf(var[co1] + EPSV);
            float bi1 = bet[co1] - mu[co1] * s1;
            float w20 = w2[co0];
            float w21 = w2[co1];
#pragma unroll
            for (int mi = 0; mi < 4; mi++) {
                pa[mi] += (d[mi][ni][0] * s0 + bi0) * w20 + (d[mi][ni][1] * s1 + bi1) * w21;
                pb[mi] += (d[mi][ni][2] * s0 + bi0) * w20 + (d[mi][ni][3] * s1 + bi1) * w21;
            }
        }
#pragma unroll
        for (int mi = 0; mi < 4; mi++) {
            pa[mi] += __shfl_xor_sync(0xffffffffu, pa[mi], 1);
            pa[mi] += __shfl_xor_sync(0xffffffffu, pa[mi], 2);
            pb[mi] += __shfl_xor_sync(0xffffffffu, pb[mi], 1);
            pb[mi] += __shfl_xor_sync(0xffffffffu, pb[mi], 2);
        }
        if (kc == 0) {
#pragma unroll
            for (int mi = 0; mi < 4; mi++) {
                red[nw][mw][mi * 16 + l4]     = pa[mi];
                red[nw][mw][mi * 16 + l4 + 8] = pb[mi];
            }
        }
        __syncthreads();
        int mwp = tid >> 6;
        int xp = tid & 63;
        part[pass * (BDIM * 4096) + (b << 12) + (y0 + mwp) * 64 + xp] =
            red[0][mwp][xp] + red[1][mwp][xp];
    }
}

// ---------------------------------------------------------------------------
// collapse: g_small = sum of 4 pass partials + o2 bias
// ---------------------------------------------------------------------------
__global__ void collapse(const float* __restrict__ part,
                         const float* __restrict__ bias) {
    int i = blockIdx.x * 256 + threadIdx.x;
    if (i < BDIM * 4096)
        g_small[i] = ((part[i] + part[BDIM * 4096 + i]) +
                      (part[2 * BDIM * 4096 + i] + part[3 * BDIM * 4096 + i])) + bias[0];
}

// ---------------------------------------------------------------------------
// bilinear x8 upsample (align_corners=True)
// ---------------------------------------------------------------------------
__global__ void upsample8(float* __restrict__ out) {
    int idx = blockIdx.x * blockDim.x + threadIdx.x;
    if (idx >= BDIM * 512 * 512) return;
    int ox = idx & 511;
    int oy = (idx >> 9) & 511;
    int b  = idx >> 18;
    const float sc = 63.0f / 511.0f;
    float fy = (float)oy * sc;
    float fx = (float)ox * sc;
    int y0 = (int)floorf(fy); int y1 = min(y0 + 1, 63);
    int x0 = (int)floorf(fx); int x1 = min(x0 + 1, 63);
    float wy = fy - (float)y0;
    float wx = fx - (float)x0;
    const float* p = g_small + (b << 12);
    float r0 = p[y0 * 64 + x0] * (1.f - wy) + p[y1 * 64 + x0] * wy;
    float r1 = p[y0 * 64 + x1] * (1.f - wy) + p[y1 * 64 + x1] * wy;
    out[idx] = r0 * (1.f - wx) + r1 * wx;
}

// ---------------------------------------------------------------------------
extern "C" void kernel_launch(void* const* d_in, const int* in_sizes, int n_in,
                              void* d_out, int out_size) {
    const float* coarse = (const float*)d_in[0];
    const float* x2     = (const float*)d_in[1];
    const float* x3     = (const float*)d_in[2];
    const float* raw    = (const float*)d_in[3];
    const float* dec_w = (const float*)d_in[6];
    const float* dec_g = (const float*)d_in[7];
    const float* dec_b = (const float*)d_in[8];
    const float* dec_m = (const float*)d_in[9];
    const float* dec_v = (const float*)d_in[10];
    const float* cc_w  = (const float*)d_in[11];
    const float* cc_g  = (const float*)d_in[12];
    const float* cc_b  = (const float*)d_in[13];
    const float* cc_m  = (const float*)d_in[14];
    const float* cc_v  = (const float*)d_in[15];
    const float* o1_w  = (const float*)d_in[16];
    const float* o1_g  = (const float*)d_in[17];
    const float* o1_b  = (const float*)d_in[18];
    const float* o1_m  = (const float*)d_in[19];
    const float* o1_v  = (const float*)d_in[20];
    const float* o2_w  = (const float*)d_in[21];
    const float* o2_b  = (const float*)d_in[22];

    __half *cat1h, *cat2h, *midh, *wdh, *wch, *woh;
    float *partp;
    cudaGetSymbolAddress((void**)&cat1h, g_cat1h);
    cudaGetSymbolAddress((void**)&cat2h, g_cat2h);
    cudaGetSymbolAddress((void**)&midh,  g_midh);
    cudaGetSymbolAddress((void**)&partp, g_part);
    cudaGetSymbolAddress((void**)&wdh, g_wdh);
    cudaGetSymbolAddress((void**)&wch, g_wch);
    cudaGetSymbolAddress((void**)&woh, g_woh);

    cudaFuncSetAttribute(conv3x3_h,
                         cudaFuncAttributeMaxDynamicSharedMemorySize, SMEM_BYTES);
    cudaFuncSetAttribute(wtrans2,
                         cudaFuncAttributeMaxDynamicSharedMemorySize, WT_SMEM);

    // launch 0: coalesced weight transforms (one block per conv x cout)
    wtrans2<<<3 * CMID, 256, WT_SMEM>>>(dec_w, cc_w, o1_w, wdh, wch, woh);
    // launch 1: input packing
    pack_all<<<BDIM * 102 * 64, 256>>>(coarse, x2, x3, raw, cat1h, cat2h);

    dim3 cgrid(128, 4);
    // launch 2: dec  cat1h(576) -> cat2h chunks [48,84)
    conv3x3_h<<<cgrid, 256, SMEM_BYTES>>>(cat1h, CMID, wdh,
        dec_g, dec_b, dec_m, dec_v, cat2h, 102, 48, nullptr, nullptr);
    // launch 3: cc   cat2h(1632) -> midh
    conv3x3_h<<<cgrid, 256, SMEM_BYTES>>>(cat2h, CCAT, wch,
        cc_g, cc_b, cc_m, cc_v, midh, 36, 0, nullptr, nullptr);
    // launch 4: o1 + fused conv1x1 -> per-pass partials
    conv3x3_h<<<cgrid, 256, SMEM_BYTES>>>(midh, CMID, woh,
        o1_g, o1_b, o1_m, o1_v, nullptr, 0, 0, o2_w, partp);

    // launch 5: collapse partials + bias
    collapse<<<(BDIM * 4096 + 255) / 256, 256>>>(partp, o2_b);
    // launch 6: upsample
    upsample8<<<(BDIM * 512 * 512 + 255) / 256, 256>>>((float*)d_out);
}